// round 13
// baseline (speedup 1.0000x reference)
#include <cuda_runtime.h>

#define CAPR 64
#define CAPC 64
#define CAPE 320
#define MAXN 4096
#define PAD  32      // one counter per 128B L2 line

// -------- static scratch (no allocations allowed) --------
// Zero-initialized at module load; counters reset in k2/k3 so every call
// (including graph replays) observes zeroed state.
__device__ int   g_cnt_row[MAXN * PAD];    // CM CSR bucket counts
__device__ int2  g_rbuf[MAXN * CAPR];      // (col, bits(-v))
__device__ int   g_cnt_col[MAXN * PAD];    // CM contributor counts
__device__ int2  g_cbuf[MAXN * CAPC];      // (src row k, bits(-v))
__device__ int   g_cnt_ext[MAXN * PAD];    // LOC/IU off-diag items per row
__device__ int2  g_ebuf[MAXN * CAPE];      // (col, bits(val))
__device__ float g_rowsum[MAXN * PAD];     // S_k of CM row k
__device__ float g_diag[MAXN * PAD];       // LOC/IU diagonal accumulation

// ============ K1: bin everything (batched items per thread for MLP) =========
__global__ void k1_bin(const int* __restrict__ row,
                       const int* __restrict__ col,
                       const float* __restrict__ data,
                       const float* __restrict__ cmw, int nnz, int cmStride,
                       const int* __restrict__ locInd,
                       const float* __restrict__ locFl,
                       const float* __restrict__ locw,
                       int mloc, int locStride, const int* __restrict__ widthp,
                       const int* __restrict__ iuInd,
                       const float* __restrict__ iuFl,
                       const int* __restrict__ iuNb,
                       const float* __restrict__ iuw,
                       int miu, int iuStride, int nbCM, int nbLoc) {
    int b = blockIdx.x;
    if (b < nbCM) {
        int t0 = b * blockDim.x + threadIdx.x;
        #pragma unroll
        for (int rep = 0; rep < 4; rep++) {
            int t = t0 + rep * cmStride;
            if (t < nnz) {
                int r = row[t];
                int c = col[t];
                float v = data[t] * cmw[r];
                int s = atomicAdd(&g_cnt_row[r * PAD], 1);
                if (s < CAPR) g_rbuf[r * CAPR + s] = make_int2(c, __float_as_int(-v));
                int s2 = atomicAdd(&g_cnt_col[c * PAD], 1);
                if (s2 < CAPC) g_cbuf[c * CAPC + s2] = make_int2(r, __float_as_int(-v));
                atomicAdd(&g_rowsum[r * PAD], v);   // no-return RED
            }
        }
        return;
    }
    b -= nbCM;
    if (b < nbLoc) {
        int t0 = b * blockDim.x + threadIdx.x;
        int W = widthp[0];
        #pragma unroll
        for (int rep = 0; rep < 2; rep++) {
            int t = t0 + rep * locStride;
            if (t < mloc * 9) {
                int mi = t / 9, j = t - mi * 9;
                int ind = locInd[mi];
                float h = 0.5f * locFl[(size_t)j * 9 * mloc + mi] * locw[ind];
                int r = ind - 1 - W;
                int c = ind + (j / 3 - 1) + (j % 3 - 1) * W;
                int s = atomicAdd(&g_cnt_ext[r * PAD], 1);
                if (s < CAPE) g_ebuf[r * CAPE + s] = make_int2(c, __float_as_int(-h));
                int s2 = atomicAdd(&g_cnt_ext[c * PAD], 1);
                if (s2 < CAPE) g_ebuf[c * CAPE + s2] = make_int2(r, __float_as_int(-h));
                atomicAdd(&g_diag[r * PAD], h);
                atomicAdd(&g_diag[c * PAD], h);
            }
        }
        return;
    }
    b -= nbLoc;
    {
        int t0 = b * blockDim.x + threadIdx.x;
        #pragma unroll
        for (int rep = 0; rep < 2; rep++) {
            int t = t0 + rep * iuStride;
            if (t < miu * 5) {
                int mi = t / 5, j = t - mi * 5;
                int r = iuInd[mi];
                float h = 0.5f * iuFl[mi * 5 + j] * iuw[r];
                int c = iuNb[mi * 5 + j];
                int s = atomicAdd(&g_cnt_ext[r * PAD], 1);
                if (s < CAPE) g_ebuf[r * CAPE + s] = make_int2(c, __float_as_int(-h));
                int s2 = atomicAdd(&g_cnt_ext[c * PAD], 1);
                if (s2 < CAPE) g_ebuf[c * CAPE + s2] = make_int2(r, __float_as_int(-h));
                atomicAdd(&g_diag[r * PAD], h);
                atomicAdd(&g_diag[c * PAD], h);
            }
        }
    }
}

// ============ K2: one 128-thread block builds one complete row of A =========
// Flat slot-indexed gather: all contributor metadata loaded in parallel once,
// then every g_rbuf load in the main loop is independent (high MLP).
__global__ void __launch_bounds__(128) k2_rows(
        float* __restrict__ A, float* __restrict__ bvec, int n,
        const float* __restrict__ ku, const float* __restrict__ conf,
        const float* __restrict__ lmb, const float* __restrict__ known,
        const float* __restrict__ kToU) {
    __shared__ float rowbuf[MAXN];
    __shared__ int   skk[CAPC + 1];
    __shared__ float scf[CAPC + 1];
    __shared__ float ssk[CAPC + 1];
    __shared__ int   scnt[CAPC + 1];

    int a = blockIdx.x;
    int tid = threadIdx.x;

    int cc = g_cnt_col[a * PAD]; if (cc > CAPC) cc = CAPC;
    int ce = g_cnt_ext[a * PAD]; if (ce > CAPE) ce = CAPE;

    // Phase A: contributor metadata, fully parallel (one latency chain total).
    if (tid <= cc) {
        int k; float coef = 0.f;
        if (tid < cc) {
            int2 e = g_cbuf[a * CAPC + tid];
            k = e.x;
            coef = __int_as_float(e.y);
        } else {
            k = a;                       // virtual diagonal contributor
        }
        int ck = g_cnt_row[k * PAD]; if (ck > CAPR) ck = CAPR;
        float Sk = g_rowsum[k * PAD];
        if (tid == cc) coef = Sk;        // its coefficient is S_a
        skk[tid]  = k;
        scf[tid]  = coef;
        ssk[tid]  = Sk;
        scnt[tid] = ck;
    }

    float4* rb4 = (float4*)rowbuf;
    float4 z = make_float4(0.f, 0.f, 0.f, 0.f);
    int n4 = n >> 2;
    #pragma unroll 8
    for (int i = tid; i < n4; i += 128) rb4[i] = z;
    __syncthreads();

    // Phase B: flat gather over all (cc+1)*CAPR slots; loads independent.
    int totSlots = (cc + 1) << 6;        // CAPR == 64
    for (int i = tid; i < totSlots; i += 128) {
        int it = i >> 6, j = i & 63;
        if (j < scnt[it]) {
            int2 e = g_rbuf[skk[it] * CAPR + j];
            atomicAdd(&rowbuf[e.x], scf[it] * __int_as_float(e.y));
        }
    }
    // per-contributor diagonal term: coef_k * S_k lands on column k
    if (tid <= cc) atomicAdd(&rowbuf[skk[tid]], scf[tid] * ssk[tid]);

    // LOC/IU off-diagonal items (independent loads)
    for (int i = tid; i < ce; i += 128) {
        int2 e = g_ebuf[a * CAPE + i];
        atomicAdd(&rowbuf[e.x], __int_as_float(e.y));
    }

    // diagonal (LOC/IU + regularization) + b; reset row-private scratch
    if (tid == 0) {
        float d = ku[a] * conf[a] + lmb[0] * known[a];
        atomicAdd(&rowbuf[a], d + g_diag[a * PAD]);
        bvec[a] = d * kToU[a];
        g_diag[a * PAD]    = 0.f;
        g_cnt_col[a * PAD] = 0;
        g_cnt_ext[a * PAD] = 0;
    }
    __syncthreads();

    float4* dst = (float4*)(A + (size_t)a * n);
    #pragma unroll 8
    for (int i = tid; i < n4; i += 128) dst[i] = rb4[i];
}

// ============ K3: reset cross-block-read scratch + tail-poison cleanup ======
__global__ void k3_reset(float* __restrict__ out, int n, long total) {
    int i = blockIdx.x * blockDim.x + threadIdx.x;
    if (i < n) { g_cnt_row[i * PAD] = 0; g_rowsum[i * PAD] = 0.f; }
    long base = (long)n * n + n;
    long extra = total - base;
    if (extra > 0) {
        long stride = (long)gridDim.x * blockDim.x;
        for (long p = (long)blockIdx.x * blockDim.x + threadIdx.x; p < extra; p += stride)
            out[base + p] = 0.f;
    }
}

extern "C" void kernel_launch(void* const* d_in, const int* in_sizes, int n_in,
                              void* d_out, int out_size) {
    // 0 height, 1 width, 2 CM_weights, 3 LOC_weights, 4 IU_weights,
    // 5 KU_weights, 6 lmbda, 7 kToUconf, 8 known, 9 kToU,
    // 10 Wcm_row, 11 Wcm_col, 12 Wcm_data, 13 LOC_inInd, 14 LOC_flows,
    // 15 IU_inInd, 16 IU_flows, 17 IU_neighInd
    const int*   width   = (const int*)d_in[1];
    const float* CMw     = (const float*)d_in[2];
    const float* LOCw    = (const float*)d_in[3];
    const float* IUw     = (const float*)d_in[4];
    const float* KUw     = (const float*)d_in[5];
    const float* lmbda   = (const float*)d_in[6];
    const float* conf    = (const float*)d_in[7];
    const float* known   = (const float*)d_in[8];
    const float* kToU    = (const float*)d_in[9];
    const int*   wr      = (const int*)d_in[10];
    const int*   wc      = (const int*)d_in[11];
    const float* wd      = (const float*)d_in[12];
    const int*   locInd  = (const int*)d_in[13];
    const float* locFl   = (const float*)d_in[14];
    const int*   iuInd   = (const int*)d_in[15];
    const float* iuFl    = (const float*)d_in[16];
    const int*   iuNb    = (const int*)d_in[17];

    int N    = in_sizes[2];
    int NNZ  = in_sizes[10];
    int MLOC = in_sizes[13];
    int MIU  = in_sizes[15];

    float* A = (float*)d_out;
    float* b = A + (size_t)N * N;
    long total = (long)out_size;

    const int T = 256;
    int nbCM      = ((NNZ + 3) / 4 + T - 1) / T;
    int cmStride  = nbCM * T;
    int nbLoc     = ((MLOC * 9 + 1) / 2 + T - 1) / T;
    int locStride = nbLoc * T;
    int nbIu      = ((MIU * 5 + 1) / 2 + T - 1) / T;
    int iuStride  = nbIu * T;
    k1_bin<<<nbCM + nbLoc + nbIu, T>>>(wr, wc, wd, CMw, NNZ, cmStride,
                                       locInd, locFl, LOCw, MLOC, locStride, width,
                                       iuInd, iuFl, iuNb, IUw, MIU, iuStride,
                                       nbCM, nbLoc);

    k2_rows<<<N, 128>>>(A, b, N, KUw, conf, lmbda, known, kToU);

    k3_reset<<<64, 128>>>(A, N, total);
}

// round 14
// speedup vs baseline: 1.1298x; 1.1298x over previous
#include <cuda_runtime.h>

#define CAPR 64
#define CAPC 64
#define CAPE 320
#define MAXN 4096
#define PAD  32      // one hot counter per 128B L2 line

// -------- static scratch (no allocations allowed) --------
// Zero-initialized at module load; counters reset in k1b/k2 so every call
// (including graph replays) observes zeroed state.
__device__ int   g_cnt_row[MAXN * PAD];    // CM CSR bucket counts (atomic, reset by k1b)
__device__ int4  g_rbuf[MAXN * CAPR / 2];  // row buckets: pairs of (col, bits(-v))
__device__ int   g_cnt_col[MAXN * PAD];    // CM contributor counts (atomic, reset by k2)
__device__ int2  g_cbuf[MAXN * CAPC];      // (src row k, bits(-v))
__device__ int   g_cnt_ext[MAXN * PAD];    // LOC/IU off-diag items (atomic, reset by k2)
__device__ int2  g_ebuf[MAXN * CAPE];      // (col, bits(val))
__device__ int   g_cntc[MAXN];             // compact clamped row counts (plain store)
__device__ float g_rowsumc[MAXN];          // compact rowsums (plain store)
__device__ float g_diag[MAXN * PAD];       // LOC/IU diagonal accumulation (reset by k2)

// ============ K1: bin everything (1 item/thread, max thread-level parallelism)
__global__ void k1_bin(const int* __restrict__ row,
                       const int* __restrict__ col,
                       const float* __restrict__ data,
                       const float* __restrict__ cmw, int nnz,
                       const int* __restrict__ locInd,
                       const float* __restrict__ locFl,
                       const float* __restrict__ locw,
                       int mloc, const int* __restrict__ widthp,
                       const int* __restrict__ iuInd,
                       const float* __restrict__ iuFl,
                       const int* __restrict__ iuNb,
                       const float* __restrict__ iuw,
                       int miu, int nbCM, int nbLoc) {
    int b = blockIdx.x;
    int2* rbuf2 = (int2*)g_rbuf;
    if (b < nbCM) {
        int t = b * blockDim.x + threadIdx.x;
        if (t >= nnz) return;
        int r = row[t];
        int c = col[t];
        float v = data[t] * cmw[r];
        int s = atomicAdd(&g_cnt_row[r * PAD], 1);
        if (s < CAPR) rbuf2[r * CAPR + s] = make_int2(c, __float_as_int(-v));
        int s2 = atomicAdd(&g_cnt_col[c * PAD], 1);
        if (s2 < CAPC) g_cbuf[c * CAPC + s2] = make_int2(r, __float_as_int(-v));
        return;
    }
    b -= nbCM;
    if (b < nbLoc) {
        int t = b * blockDim.x + threadIdx.x;
        if (t >= mloc * 9) return;
        int mi = t / 9, j = t - mi * 9;
        int W = widthp[0];
        int ind = locInd[mi];
        float h = 0.5f * locFl[(size_t)j * 9 * mloc + mi] * locw[ind];
        int r = ind - 1 - W;
        int c = ind + (j / 3 - 1) + (j % 3 - 1) * W;
        int s = atomicAdd(&g_cnt_ext[r * PAD], 1);
        if (s < CAPE) g_ebuf[r * CAPE + s] = make_int2(c, __float_as_int(-h));
        int s2 = atomicAdd(&g_cnt_ext[c * PAD], 1);
        if (s2 < CAPE) g_ebuf[c * CAPE + s2] = make_int2(r, __float_as_int(-h));
        atomicAdd(&g_diag[r * PAD], h);
        atomicAdd(&g_diag[c * PAD], h);
        return;
    }
    b -= nbLoc;
    {
        int t = b * blockDim.x + threadIdx.x;
        if (t >= miu * 5) return;
        int mi = t / 5, j = t - mi * 5;
        int r = iuInd[mi];
        float h = 0.5f * iuFl[mi * 5 + j] * iuw[r];
        int c = iuNb[mi * 5 + j];
        int s = atomicAdd(&g_cnt_ext[r * PAD], 1);
        if (s < CAPE) g_ebuf[r * CAPE + s] = make_int2(c, __float_as_int(-h));
        int s2 = atomicAdd(&g_cnt_ext[c * PAD], 1);
        if (s2 < CAPE) g_ebuf[c * CAPE + s2] = make_int2(r, __float_as_int(-h));
        atomicAdd(&g_diag[r * PAD], h);
        atomicAdd(&g_diag[c * PAD], h);
    }
}

// ============ K1b: rowsums from buckets (warp/row), compact counts, reset ===
__global__ void k1b_rowsum(int n) {
    int w = threadIdx.x >> 5, lane = threadIdx.x & 31;
    int r = blockIdx.x * 8 + w;
    if (r >= n) return;
    int cnt = g_cnt_row[r * PAD]; if (cnt > CAPR) cnt = CAPR;
    const int2* rbuf2 = (const int2*)g_rbuf;
    float s = 0.f;
    if (lane < cnt)      s += __int_as_float(rbuf2[r * CAPR + lane].y);
    if (lane + 32 < cnt) s += __int_as_float(rbuf2[r * CAPR + lane + 32].y);
    #pragma unroll
    for (int o = 16; o; o >>= 1) s += __shfl_xor_sync(0xffffffffu, s, o);
    if (lane == 0) {
        g_rowsumc[r]       = -s;   // stored vals are -v; rowsum S = -(sum)
        g_cntc[r]          = cnt;
        g_cnt_row[r * PAD] = 0;    // reset for next call
    }
}

// ============ K2: one 256-thread block builds one complete row of A =========
__global__ void __launch_bounds__(256) k2_rows(
        float* __restrict__ A, float* __restrict__ bvec, int n, long total,
        const float* __restrict__ ku, const float* __restrict__ conf,
        const float* __restrict__ lmb, const float* __restrict__ known,
        const float* __restrict__ kToU) {
    __shared__ float rowbuf[MAXN];
    __shared__ int   skk[CAPC + 1];
    __shared__ float scf[CAPC + 1];
    __shared__ float ssk[CAPC + 1];
    __shared__ int   scnt[CAPC + 1];

    int a = blockIdx.x;
    int tid = threadIdx.x;

    int cc = g_cnt_col[a * PAD]; if (cc > CAPC) cc = CAPC;
    int ce = g_cnt_ext[a * PAD]; if (ce > CAPE) ce = CAPE;

    // Phase A: contributor metadata, fully parallel.
    if (tid <= cc) {
        int k; float coef = 0.f;
        if (tid < cc) {
            int2 e = g_cbuf[a * CAPC + tid];
            k = e.x;
            coef = __int_as_float(e.y);
        } else {
            k = a;                        // virtual diagonal contributor
        }
        float Sk = g_rowsumc[k];
        if (tid == cc) coef = Sk;         // its coefficient is S_a
        skk[tid]  = k;
        scf[tid]  = coef;
        ssk[tid]  = Sk;
        scnt[tid] = g_cntc[k];
    }

    float4* rb4 = (float4*)rowbuf;
    float4 z = make_float4(0.f, 0.f, 0.f, 0.f);
    int n4 = n >> 2;
    #pragma unroll 4
    for (int i = tid; i < n4; i += 256) rb4[i] = z;
    __syncthreads();

    // Phase B: flat gather, int4 = 2 bucket slots per load.
    int totG = (cc + 1) << 5;             // 32 slot-pairs per contributor
    for (int i = tid; i < totG; i += 256) {
        int it = i >> 5, g = i & 31;
        int cnt = scnt[it];
        int j = g << 1;
        if (j < cnt) {
            int4 e = g_rbuf[(skk[it] << 5) + g];
            float cf = scf[it];
            atomicAdd(&rowbuf[e.x], cf * __int_as_float(e.y));
            if (j + 1 < cnt)
                atomicAdd(&rowbuf[e.z], cf * __int_as_float(e.w));
        }
    }
    // per-contributor diagonal term: coef_k * S_k lands on column k
    if (tid <= cc) atomicAdd(&rowbuf[skk[tid]], scf[tid] * ssk[tid]);

    // LOC/IU off-diagonal items
    for (int i = tid; i < ce; i += 256) {
        int2 e = g_ebuf[a * CAPE + i];
        atomicAdd(&rowbuf[e.x], __int_as_float(e.y));
    }

    // diagonal (LOC/IU + regularization) + b; reset row-private scratch
    if (tid == 0) {
        float d = ku[a] * conf[a] + lmb[0] * known[a];
        atomicAdd(&rowbuf[a], d + g_diag[a * PAD]);
        bvec[a] = d * kToU[a];
        g_diag[a * PAD]    = 0.f;
        g_cnt_col[a * PAD] = 0;
        g_cnt_ext[a * PAD] = 0;
    }

    // tail-poison cleanup beyond A+b (normally zero elements -> free)
    if (a == 0) {
        long base = (long)n * n + n;
        for (long p = base + tid; p < total; p += 256) A[p] = 0.f;
    }
    __syncthreads();

    float4* dst = (float4*)(A + (size_t)a * n);
    #pragma unroll 4
    for (int i = tid; i < n4; i += 256) dst[i] = rb4[i];
}

extern "C" void kernel_launch(void* const* d_in, const int* in_sizes, int n_in,
                              void* d_out, int out_size) {
    // 0 height, 1 width, 2 CM_weights, 3 LOC_weights, 4 IU_weights,
    // 5 KU_weights, 6 lmbda, 7 kToUconf, 8 known, 9 kToU,
    // 10 Wcm_row, 11 Wcm_col, 12 Wcm_data, 13 LOC_inInd, 14 LOC_flows,
    // 15 IU_inInd, 16 IU_flows, 17 IU_neighInd
    const int*   width   = (const int*)d_in[1];
    const float* CMw     = (const float*)d_in[2];
    const float* LOCw    = (const float*)d_in[3];
    const float* IUw     = (const float*)d_in[4];
    const float* KUw     = (const float*)d_in[5];
    const float* lmbda   = (const float*)d_in[6];
    const float* conf    = (const float*)d_in[7];
    const float* known   = (const float*)d_in[8];
    const float* kToU    = (const float*)d_in[9];
    const int*   wr      = (const int*)d_in[10];
    const int*   wc      = (const int*)d_in[11];
    const float* wd      = (const float*)d_in[12];
    const int*   locInd  = (const int*)d_in[13];
    const float* locFl   = (const float*)d_in[14];
    const int*   iuInd   = (const int*)d_in[15];
    const float* iuFl    = (const float*)d_in[16];
    const int*   iuNb    = (const int*)d_in[17];

    int N    = in_sizes[2];
    int NNZ  = in_sizes[10];
    int MLOC = in_sizes[13];
    int MIU  = in_sizes[15];

    float* A = (float*)d_out;
    float* b = A + (size_t)N * N;
    long total = (long)out_size;

    const int T = 256;
    int nbCM  = (NNZ + T - 1) / T;
    int nbLoc = (MLOC * 9 + T - 1) / T;
    int nbIu  = (MIU * 5 + T - 1) / T;
    k1_bin<<<nbCM + nbLoc + nbIu, T>>>(wr, wc, wd, CMw, NNZ,
                                       locInd, locFl, LOCw, MLOC, width,
                                       iuInd, iuFl, iuNb, IUw, MIU,
                                       nbCM, nbLoc);

    k1b_rowsum<<<(N + 7) / 8, 256>>>(N);

    k2_rows<<<N, 256>>>(A, b, N, total, KUw, conf, lmbda, known, kToU);
}

// round 15
// speedup vs baseline: 1.1599x; 1.0267x over previous
#include <cuda_runtime.h>
#include <cstdint>

#define CAPR 64
#define CAPC 64
#define CAPE 320
#define MAXN 4096
#define PAD  32      // one hot counter per 128B L2 line

// -------- static scratch (no allocations allowed) --------
// Zero-initialized at module load; counters reset in k1b/k2 so every call
// (including graph replays) observes zeroed state.
__device__ int   g_cnt_row[MAXN * PAD];    // CM CSR bucket counts (reset by k1b)
__device__ int4  g_rbuf[MAXN * CAPR / 2];  // row buckets: pairs of (col, bits(-v))
__device__ int   g_cnt_col[MAXN * PAD];    // CM contributor counts (reset by k2)
__device__ int2  g_cbuf[MAXN * CAPC];      // (src row k, bits(-v))
__device__ int   g_cnt_ext[MAXN * PAD];    // LOC/IU off-diag items (reset by k2)
__device__ int2  g_ebuf[MAXN * CAPE];      // (col, bits(-h))
__device__ int   g_cntc[MAXN];             // compact clamped row counts
__device__ float g_rowsumc[MAXN];          // compact rowsums

__device__ __forceinline__ uint32_t smem_u32(const void* p) {
    return (uint32_t)__cvta_generic_to_shared(p);
}

// ============ K1: bin everything (1 item/thread) ============================
__global__ void k1_bin(const int* __restrict__ row,
                       const int* __restrict__ col,
                       const float* __restrict__ data,
                       const float* __restrict__ cmw, int nnz,
                       const int* __restrict__ locInd,
                       const float* __restrict__ locFl,
                       const float* __restrict__ locw,
                       int mloc, const int* __restrict__ widthp,
                       const int* __restrict__ iuInd,
                       const float* __restrict__ iuFl,
                       const int* __restrict__ iuNb,
                       const float* __restrict__ iuw,
                       int miu, int nbCM, int nbLoc) {
    int b = blockIdx.x;
    int2* rbuf2 = (int2*)g_rbuf;
    if (b < nbCM) {
        int t = b * blockDim.x + threadIdx.x;
        if (t >= nnz) return;
        int r = row[t];
        int c = col[t];
        float v = data[t] * cmw[r];
        int s = atomicAdd(&g_cnt_row[r * PAD], 1);
        if (s < CAPR) rbuf2[r * CAPR + s] = make_int2(c, __float_as_int(-v));
        int s2 = atomicAdd(&g_cnt_col[c * PAD], 1);
        if (s2 < CAPC) g_cbuf[c * CAPC + s2] = make_int2(r, __float_as_int(-v));
        return;
    }
    b -= nbCM;
    if (b < nbLoc) {
        int t = b * blockDim.x + threadIdx.x;
        if (t >= mloc * 9) return;
        int mi = t / 9, j = t - mi * 9;
        int W = widthp[0];
        int ind = locInd[mi];
        float h = 0.5f * locFl[(size_t)j * 9 * mloc + mi] * locw[ind];
        int r = ind - 1 - W;
        int c = ind + (j / 3 - 1) + (j % 3 - 1) * W;
        int s = atomicAdd(&g_cnt_ext[r * PAD], 1);
        if (s < CAPE) g_ebuf[r * CAPE + s] = make_int2(c, __float_as_int(-h));
        int s2 = atomicAdd(&g_cnt_ext[c * PAD], 1);
        if (s2 < CAPE) g_ebuf[c * CAPE + s2] = make_int2(r, __float_as_int(-h));
        return;
    }
    b -= nbLoc;
    {
        int t = b * blockDim.x + threadIdx.x;
        if (t >= miu * 5) return;
        int mi = t / 5, j = t - mi * 5;
        int r = iuInd[mi];
        float h = 0.5f * iuFl[mi * 5 + j] * iuw[r];
        int c = iuNb[mi * 5 + j];
        int s = atomicAdd(&g_cnt_ext[r * PAD], 1);
        if (s < CAPE) g_ebuf[r * CAPE + s] = make_int2(c, __float_as_int(-h));
        int s2 = atomicAdd(&g_cnt_ext[c * PAD], 1);
        if (s2 < CAPE) g_ebuf[c * CAPE + s2] = make_int2(r, __float_as_int(-h));
    }
}

// ============ K1b: rowsums from buckets (warp/row), compact counts, reset ===
__global__ void k1b_rowsum(int n) {
    int w = threadIdx.x >> 5, lane = threadIdx.x & 31;
    int r = blockIdx.x * 8 + w;
    if (r >= n) return;
    int cnt = g_cnt_row[r * PAD]; if (cnt > CAPR) cnt = CAPR;
    const int2* rbuf2 = (const int2*)g_rbuf;
    float s = 0.f;
    if (lane < cnt)      s += __int_as_float(rbuf2[r * CAPR + lane].y);
    if (lane + 32 < cnt) s += __int_as_float(rbuf2[r * CAPR + lane + 32].y);
    #pragma unroll
    for (int o = 16; o; o >>= 1) s += __shfl_xor_sync(0xffffffffu, s, o);
    if (lane == 0) {
        g_rowsumc[r]       = -s;   // stored vals are -v; rowsum S = -(sum)
        g_cntc[r]          = cnt;
        g_cnt_row[r * PAD] = 0;    // reset for next call
    }
}

// ============ K2: one 256-thread block builds one complete row of A =========
// Row written back with a single 1D TMA bulk copy (smem -> gmem): frees the
// LSU from the STG.128 issue cost and the smem readback.
__global__ void __launch_bounds__(256) k2_rows(
        float* __restrict__ A, float* __restrict__ bvec, int n, long total,
        const float* __restrict__ ku, const float* __restrict__ conf,
        const float* __restrict__ lmb, const float* __restrict__ known,
        const float* __restrict__ kToU) {
    __shared__ __align__(16) float rowbuf[MAXN];
    __shared__ int   skk[CAPC + 1];
    __shared__ float scf[CAPC + 1];
    __shared__ float ssk[CAPC + 1];
    __shared__ int   scnt[CAPC + 1];

    int a = blockIdx.x;
    int tid = threadIdx.x;

    int cc = g_cnt_col[a * PAD]; if (cc > CAPC) cc = CAPC;
    int ce = g_cnt_ext[a * PAD]; if (ce > CAPE) ce = CAPE;

    // Phase A: contributor metadata, fully parallel.
    if (tid <= cc) {
        int k; float coef = 0.f;
        if (tid < cc) {
            int2 e = g_cbuf[a * CAPC + tid];
            k = e.x;
            coef = __int_as_float(e.y);
        } else {
            k = a;                        // virtual diagonal contributor
        }
        float Sk = g_rowsumc[k];
        if (tid == cc) coef = Sk;         // its coefficient is S_a
        skk[tid]  = k;
        scf[tid]  = coef;
        ssk[tid]  = Sk;
        scnt[tid] = g_cntc[k];
    }

    float4* rb4 = (float4*)rowbuf;
    float4 z = make_float4(0.f, 0.f, 0.f, 0.f);
    int n4 = n >> 2;
    #pragma unroll 4
    for (int i = tid; i < n4; i += 256) rb4[i] = z;
    __syncthreads();

    // Phase B: flat gather, int4 = 2 bucket slots per load.
    int totG = (cc + 1) << 5;             // 32 slot-pairs per contributor
    for (int i = tid; i < totG; i += 256) {
        int it = i >> 5, g = i & 31;
        int cnt = scnt[it];
        int j = g << 1;
        if (j < cnt) {
            int4 e = g_rbuf[(skk[it] << 5) + g];
            float cf = scf[it];
            atomicAdd(&rowbuf[e.x], cf * __int_as_float(e.y));
            if (j + 1 < cnt)
                atomicAdd(&rowbuf[e.z], cf * __int_as_float(e.w));
        }
    }
    // per-contributor diagonal term: coef_k * S_k lands on column k
    if (tid <= cc) atomicAdd(&rowbuf[skk[tid]], scf[tid] * ssk[tid]);

    // LOC/IU off-diagonal items; diagonal of row a = -sum of item values
    float dsum = 0.f;
    for (int i = tid; i < ce; i += 256) {
        int2 e = g_ebuf[a * CAPE + i];
        float v = __int_as_float(e.y);        // v = -h
        atomicAdd(&rowbuf[e.x], v);
        dsum -= v;                            // accumulate +h
    }
    if (dsum != 0.f) atomicAdd(&rowbuf[a], dsum);

    // diagonal regularization + b; reset row-private scratch
    if (tid == 0) {
        float d = ku[a] * conf[a] + lmb[0] * known[a];
        atomicAdd(&rowbuf[a], d);
        bvec[a] = d * kToU[a];
        g_cnt_col[a * PAD] = 0;
        g_cnt_ext[a * PAD] = 0;
    }

    // tail-poison cleanup beyond A+b (normally zero elements -> free)
    if (a == 0) {
        long base = (long)n * n + n;
        for (long p = base + tid; p < total; p += 256) A[p] = 0.f;
    }
    __syncthreads();

    // Row store via 1D TMA bulk copy (single thread issues; engine does copy).
    if (tid == 0) {
        asm volatile("fence.proxy.async.shared::cta;" ::: "memory");
        uint32_t src = smem_u32(rowbuf);
        float* dst = A + (size_t)a * n;
        asm volatile(
            "cp.async.bulk.global.shared::cta.bulk_group [%0], [%1], %2;"
            :: "l"(dst), "r"(src), "r"(n * 4) : "memory");
        asm volatile("cp.async.bulk.commit_group;" ::: "memory");
        asm volatile("cp.async.bulk.wait_group 0;" ::: "memory");
    }
}

extern "C" void kernel_launch(void* const* d_in, const int* in_sizes, int n_in,
                              void* d_out, int out_size) {
    // 0 height, 1 width, 2 CM_weights, 3 LOC_weights, 4 IU_weights,
    // 5 KU_weights, 6 lmbda, 7 kToUconf, 8 known, 9 kToU,
    // 10 Wcm_row, 11 Wcm_col, 12 Wcm_data, 13 LOC_inInd, 14 LOC_flows,
    // 15 IU_inInd, 16 IU_flows, 17 IU_neighInd
    const int*   width   = (const int*)d_in[1];
    const float* CMw     = (const float*)d_in[2];
    const float* LOCw    = (const float*)d_in[3];
    const float* IUw     = (const float*)d_in[4];
    const float* KUw     = (const float*)d_in[5];
    const float* lmbda   = (const float*)d_in[6];
    const float* conf    = (const float*)d_in[7];
    const float* known   = (const float*)d_in[8];
    const float* kToU    = (const float*)d_in[9];
    const int*   wr      = (const int*)d_in[10];
    const int*   wc      = (const int*)d_in[11];
    const float* wd      = (const float*)d_in[12];
    const int*   locInd  = (const int*)d_in[13];
    const float* locFl   = (const float*)d_in[14];
    const int*   iuInd   = (const int*)d_in[15];
    const float* iuFl    = (const float*)d_in[16];
    const int*   iuNb    = (const int*)d_in[17];

    int N    = in_sizes[2];
    int NNZ  = in_sizes[10];
    int MLOC = in_sizes[13];
    int MIU  = in_sizes[15];

    float* A = (float*)d_out;
    float* b = A + (size_t)N * N;
    long total = (long)out_size;

    const int T = 256;
    int nbCM  = (NNZ + T - 1) / T;
    int nbLoc = (MLOC * 9 + T - 1) / T;
    int nbIu  = (MIU * 5 + T - 1) / T;
    k1_bin<<<nbCM + nbLoc + nbIu, T>>>(wr, wc, wd, CMw, NNZ,
                                       locInd, locFl, LOCw, MLOC, width,
                                       iuInd, iuFl, iuNb, IUw, MIU,
                                       nbCM, nbLoc);

    k1b_rowsum<<<(N + 7) / 8, 256>>>(N);

    k2_rows<<<N, 256>>>(A, b, N, total, KUw, conf, lmbda, known, kToU);
}